// round 5
// baseline (speedup 1.0000x reference)
#include <cuda_runtime.h>

// FusionFeature_Layer on GB300 (sm_103a), fp32 flash-attention formulation.
//
// Shapes: B=8, C=128, h=w=56, N=3136.
//   qf[b,n,c]  = query.flat [b*N*C + n*C + c]   (raw reshape -> contiguous rows)
//   sf[b,c,m]  = support.flat[b*C*N + c*N + m]
//   A = qf @ sf  (N x N), attn = softmax(A, axis=-1), mask = sigmoid(rowsum(A))
//   out_q.flat[b, n*C+c] = q.flat[...] + (attn @ qf)[n,c] * mask[n]
//   out_s.flat[b, n*C+c] = s.flat[...] * (1 + mask[n])
//
// No max-subtraction: logits ~ N(0,128), max ~45 -> exp fits fp32. Single pass
// per 64-row tile accumulating raw sums, exp sums, and unnormalized O.

namespace {
constexpr int kB  = 8;
constexpr int kC  = 128;
constexpr int kN  = 3136;   // 56*56 = 49*64
constexpr int TM  = 64;     // row tile
constexpr int TN  = 64;     // column (m) tile, 3136/64 = 49 exact
constexpr int NTH = 128;    // threads per CTA (16 tx x 8 ty)
// smem: Qs[TM][C] + Ss[C][TN] (P aliases first TM*TN) + Vs[TN][C] + 2*TM rows
constexpr int SMEM_FLOATS = TM * kC + kC * TN + TN * kC + 2 * TM;
}

__global__ __launch_bounds__(NTH, 2)
void fusion_attn_kernel(const float* __restrict__ q,
                        const float* __restrict__ s,
                        float* __restrict__ out)
{
    extern __shared__ float smem[];
    float* Qs       = smem;                 // [TM][128]  q rows (also used in epilogue)
    float* Ss       = smem + TM * kC;       // [128][TN]  support cols; P aliases [TM][TN]
    float* Vs       = Ss + kC * TN;         // [TN][128]  V = q rows of the m-tile
    float* rowscale = Vs + TN * kC;         // [TM] mask/expsum
    float* rowmask1 = rowscale + TM;        // [TM] 1+mask

    const int tid = threadIdx.x;
    const int tx  = tid & 15;               // 0..15 -> 4 cols (GEMM1) / 8 cols (GEMM2)
    const int ty  = tid >> 4;               // 0..7  -> 8 rows
    const int b   = blockIdx.y;
    const int n0  = blockIdx.x * TM;

    const float* __restrict__ qb = q + (size_t)b * (kN * kC);
    const float* __restrict__ sb = s + (size_t)b * (kN * kC);

    // ---- Load Q tile (contiguous 32KB) ----
    {
        const float4* src = reinterpret_cast<const float4*>(qb + (size_t)n0 * kC);
        float4* dst = reinterpret_cast<float4*>(Qs);
        #pragma unroll
        for (int i = 0; i < (TM * kC / 4) / NTH; i++)
            dst[tid + i * NTH] = src[tid + i * NTH];
    }

    float O[8][8];
    #pragma unroll
    for (int i = 0; i < 8; i++)
        #pragma unroll
        for (int j = 0; j < 8; j++) O[i][j] = 0.f;
    float rawP[8], expP[8];
    #pragma unroll
    for (int i = 0; i < 8; i++) { rawP[i] = 0.f; expP[i] = 0.f; }

    for (int mt = 0; mt < kN / TN; mt++) {
        const int m0 = mt * TN;

        __syncthreads();  // previous iteration's GEMM2 done reading Ss(P)/Vs

        // ---- Load S tile: Ss[c][j] = support[b, c, m0+j] ----
        #pragma unroll
        for (int i = 0; i < 16; i++) {
            int idx = tid + i * NTH;          // 0..2047
            int c   = idx >> 4;
            int j4  = (idx & 15) << 2;
            float4 v = *reinterpret_cast<const float4*>(sb + (size_t)c * kN + m0 + j4);
            *reinterpret_cast<float4*>(Ss + c * TN + j4) = v;
        }
        // ---- Load V tile (contiguous 32KB): Vs[m][c] = qf[b, m0+m, c] ----
        {
            const float4* src = reinterpret_cast<const float4*>(qb + (size_t)m0 * kC);
            float4* dst = reinterpret_cast<float4*>(Vs);
            #pragma unroll
            for (int i = 0; i < 16; i++)
                dst[tid + i * NTH] = src[tid + i * NTH];
        }
        __syncthreads();

        // ---- GEMM1: L[8][4] = Qs[rows ty*8..][128] @ Ss[128][cols tx*4..] ----
        float L[8][4];
        #pragma unroll
        for (int i = 0; i < 8; i++)
            #pragma unroll
            for (int j = 0; j < 4; j++) L[i][j] = 0.f;

        #pragma unroll 1
        for (int kb = 0; kb < kC / 4; kb++) {
            float a_[8][4], b_[4][4];
            #pragma unroll
            for (int i = 0; i < 8; i++) {
                float4 t = *reinterpret_cast<const float4*>(&Qs[(ty * 8 + i) * kC + kb * 4]);
                a_[i][0] = t.x; a_[i][1] = t.y; a_[i][2] = t.z; a_[i][3] = t.w;
            }
            #pragma unroll
            for (int u = 0; u < 4; u++) {
                float4 t = *reinterpret_cast<const float4*>(&Ss[(kb * 4 + u) * TN + tx * 4]);
                b_[u][0] = t.x; b_[u][1] = t.y; b_[u][2] = t.z; b_[u][3] = t.w;
            }
            #pragma unroll
            for (int i = 0; i < 8; i++)
                #pragma unroll
                for (int u = 0; u < 4; u++)
                    #pragma unroll
                    for (int j = 0; j < 4; j++)
                        L[i][j] += a_[i][u] * b_[u][j];
        }
        __syncthreads();  // all GEMM1 reads of Ss finished before P overwrites it

        // ---- exp + row partials; write P into Ss region (alias) ----
        #pragma unroll
        for (int i = 0; i < 8; i++) {
            rawP[i] += (L[i][0] + L[i][1]) + (L[i][2] + L[i][3]);
            float4 p;
            p.x = __expf(L[i][0]); p.y = __expf(L[i][1]);
            p.z = __expf(L[i][2]); p.w = __expf(L[i][3]);
            expP[i] += (p.x + p.y) + (p.z + p.w);
            *reinterpret_cast<float4*>(&Ss[(ty * 8 + i) * TN + tx * 4]) = p;
        }
        __syncthreads();

        // ---- GEMM2: O[8][8] += P[rows][64] @ Vs[64][cols tx*8..] ----
        #pragma unroll 1
        for (int kb = 0; kb < TN / 4; kb++) {
            float a_[8][4], b_[4][8];
            #pragma unroll
            for (int i = 0; i < 8; i++) {
                float4 t = *reinterpret_cast<const float4*>(&Ss[(ty * 8 + i) * TN + kb * 4]);
                a_[i][0] = t.x; a_[i][1] = t.y; a_[i][2] = t.z; a_[i][3] = t.w;
            }
            #pragma unroll
            for (int u = 0; u < 4; u++) {
                float4 t0 = *reinterpret_cast<const float4*>(&Vs[(kb * 4 + u) * kC + tx * 8]);
                float4 t1 = *reinterpret_cast<const float4*>(&Vs[(kb * 4 + u) * kC + tx * 8 + 4]);
                b_[u][0] = t0.x; b_[u][1] = t0.y; b_[u][2] = t0.z; b_[u][3] = t0.w;
                b_[u][4] = t1.x; b_[u][5] = t1.y; b_[u][6] = t1.z; b_[u][7] = t1.w;
            }
            #pragma unroll
            for (int i = 0; i < 8; i++)
                #pragma unroll
                for (int u = 0; u < 4; u++)
                    #pragma unroll
                    for (int j = 0; j < 8; j++)
                        O[i][j] += a_[i][u] * b_[u][j];
        }
    }

    // ---- reduce row sums across the 16 tx lanes (lanes 0-15 / 16-31 groups) ----
    #pragma unroll
    for (int i = 0; i < 8; i++) {
        float r = rawP[i], e = expP[i];
        #pragma unroll
        for (int off = 1; off < 16; off <<= 1) {
            r += __shfl_xor_sync(0xffffffffu, r, off);
            e += __shfl_xor_sync(0xffffffffu, e, off);
        }
        if (tx == 0) {
            int rr = ty * 8 + i;
            float m = 1.f / (1.f + __expf(-r));   // sigmoid of raw row sum
            rowscale[rr] = m / e;                 // mask / softmax denominator
            rowmask1[rr] = 1.f + m;
        }
    }
    __syncthreads();

    // ---- query output: out_q = q + O * scale ----
    float* outq = out + (size_t)b * (kN * kC);
    #pragma unroll
    for (int i = 0; i < 8; i++) {
        int rr = ty * 8 + i;
        float sc = rowscale[rr];
        const float* qrow = &Qs[rr * kC + tx * 8];
        float4 q0 = *reinterpret_cast<const float4*>(qrow);
        float4 q1 = *reinterpret_cast<const float4*>(qrow + 4);
        float4 o0, o1;
        o0.x = q0.x + O[i][0] * sc; o0.y = q0.y + O[i][1] * sc;
        o0.z = q0.z + O[i][2] * sc; o0.w = q0.w + O[i][3] * sc;
        o1.x = q1.x + O[i][4] * sc; o1.y = q1.y + O[i][5] * sc;
        o1.z = q1.z + O[i][6] * sc; o1.w = q1.w + O[i][7] * sc;
        float* orow = outq + (size_t)(n0 + rr) * kC + tx * 8;
        *reinterpret_cast<float4*>(orow)     = o0;
        *reinterpret_cast<float4*>(orow + 4) = o1;
    }

    // ---- support output: out_s = s * (1 + mask[row]) ----
    float* outs = out + (size_t)kB * kN * kC + (size_t)b * (kN * kC);
    {
        const float4* src = reinterpret_cast<const float4*>(sb + (size_t)n0 * kC);
        float4* dst = reinterpret_cast<float4*>(outs + (size_t)n0 * kC);
        #pragma unroll
        for (int f0 = 0; f0 < 16; f0++) {
            int f = tid + f0 * NTH;        // 0..2047, row = f/32 (32 float4 per row)
            float m1 = rowmask1[f >> 5];
            float4 v = src[f];
            v.x *= m1; v.y *= m1; v.z *= m1; v.w *= m1;
            dst[f] = v;
        }
    }
}

extern "C" void kernel_launch(void* const* d_in, const int* in_sizes, int n_in,
                              void* d_out, int out_size)
{
    const float* q = (const float*)d_in[0];   // query_feature  [8,128,56,56]
    const float* s = (const float*)d_in[1];   // support_feature[8,128,56,56]
    float* out = (float*)d_out;               // [query_out | support_out]

    const size_t smem_bytes = (size_t)SMEM_FLOATS * sizeof(float);  // ~96.5 KB
    cudaFuncSetAttribute((const void*)fusion_attn_kernel,
                         cudaFuncAttributeMaxDynamicSharedMemorySize,
                         (int)smem_bytes);

    dim3 grid(kN / TM, kB);   // 49 x 8 = 392 CTAs
    fusion_attn_kernel<<<grid, NTH, smem_bytes>>>(q, s, out);
}